// round 1
// baseline (speedup 1.0000x reference)
#include <cuda_runtime.h>
#include <cuda_bf16.h>
#include <cstdint>

#define N_NODES   20000
#define N_INPUT   64
#define KMAX      12
#define NBITS     64
#define N_OUT     10
#define NBATCH    64
#define TSTEPS    128
#define LUTW      128         /* 4096 bits / 32 */
#define DUMMY     20000
#define ST_SZ     20008
#define GRID_MAIN 148
#define TPB_MAIN  512

// ---------------- device globals (scratch; no allocations allowed) ----------------
__device__ __align__(16) unsigned short g_adj[N_NODES * 16];   // 640 KB packed adjacency
__device__ unsigned int  g_lut[N_NODES * LUTW];                // 10.24 MB bit-packed LUT
__device__ uint2         g_st[2][ST_SZ];                       // bit-packed states (bit b = batch b), double buffered; slot 20000 = always-0 dummy
__device__ uint2         g_u[TSTEPS * 64];                     // input-layer bits u[t][j]
__device__ uint2         g_xb[NBATCH * TSTEPS];                // packed x bits [b][t]
__device__ uint2         g_wc[64];                             // packed w_in columns
__device__ unsigned int  g_arrive;
__device__ volatile unsigned int g_gen;

// ---------------- preprocessing ----------------

__global__ void k_pack_x(const int* __restrict__ x) {
    int wid  = (blockIdx.x * blockDim.x + threadIdx.x) >> 5;
    int lane = threadIdx.x & 31;
    if (wid >= NBATCH * TSTEPS) return;
    int b = wid >> 7, t = wid & 127;
    const int* p = x + ((size_t)b * TSTEPS + t) * NBITS;
    unsigned lo = __ballot_sync(0xffffffffu, p[lane] != 0);
    unsigned hi = __ballot_sync(0xffffffffu, p[lane + 32] != 0);
    if (lane == 0) g_xb[b * TSTEPS + t] = make_uint2(lo, hi);
}

__global__ void k_pack_w(const int* __restrict__ w_in) {
    int wid  = (blockIdx.x * blockDim.x + threadIdx.x) >> 5;
    int lane = threadIdx.x & 31;
    if (wid >= 64) return;
    unsigned lo = __ballot_sync(0xffffffffu, w_in[lane * 64 + wid] != 0);
    unsigned hi = __ballot_sync(0xffffffffu, w_in[(lane + 32) * 64 + wid] != 0);
    if (lane == 0) g_wc[wid] = make_uint2(lo, hi);
}

// u[t][j] bit b = ((x_bits[b][t] & w_col[j]) != 0)
__global__ void k_build_u() {
    int wid  = (blockIdx.x * blockDim.x + threadIdx.x) >> 5;
    int lane = threadIdx.x & 31;
    if (wid >= TSTEPS * 64) return;
    int t = wid >> 6, j = wid & 63;
    uint2 wc = g_wc[j];
    uint2 xa = g_xb[lane * TSTEPS + t];
    uint2 xb = g_xb[(lane + 32) * TSTEPS + t];
    unsigned lo = __ballot_sync(0xffffffffu, ((xa.x & wc.x) | (xa.y & wc.y)) != 0);
    unsigned hi = __ballot_sync(0xffffffffu, ((xb.x & wc.x) | (xb.y & wc.y)) != 0);
    if (lane == 0) g_u[t * 64 + j] = make_uint2(lo, hi);
}

// Fold adj_mask into adjacency: masked -> DUMMY (state always 0);
// no-neighbor nodes -> self at slot 11 (identity LUT written by k_pack_lut).
__global__ void k_pack_adj(const int* __restrict__ adj_list, const int* __restrict__ adj_mask) {
    int n = blockIdx.x * blockDim.x + threadIdx.x;
    if (n >= N_NODES) return;
    unsigned a[16];
    int any = 0;
#pragma unroll
    for (int k = 0; k < KMAX; k++) {
        int m = adj_mask[n * KMAX + k];
        any |= m;
        a[k] = m ? (unsigned)adj_list[n * KMAX + k] : (unsigned)DUMMY;
    }
    a[12] = a[13] = a[14] = a[15] = DUMMY;
    if (!any) {
#pragma unroll
        for (int k = 0; k < KMAX; k++) a[k] = DUMMY;
        a[11] = (unsigned)n;   // idx = old state bit
    }
    uint4 v0, v1;
    v0.x = a[0]  | (a[1]  << 16); v0.y = a[2]  | (a[3]  << 16);
    v0.z = a[4]  | (a[5]  << 16); v0.w = a[6]  | (a[7]  << 16);
    v1.x = a[8]  | (a[9]  << 16); v1.y = a[10] | (a[11] << 16);
    v1.z = a[12] | (a[13] << 16); v1.w = a[14] | (a[15] << 16);
    ((uint4*)g_adj)[n * 2]     = v0;
    ((uint4*)g_adj)[n * 2 + 1] = v1;
}

// Bit-pack the LUT: one warp per output 32-bit word. For no-neighbor nodes,
// write the identity LUT (word0 = 0b10 -> new = old state).
__global__ void k_pack_lut(const int* __restrict__ lut, const int* __restrict__ adj_mask) {
    int wid  = (blockIdx.x * blockDim.x + threadIdx.x) >> 5;
    int lane = threadIdx.x & 31;
    if (wid >= N_NODES * LUTW) return;
    int node = wid >> 7, wofs = wid & 127;
    int mv = (lane < KMAX) ? adj_mask[node * KMAX + lane] : 0;
    unsigned anym = __ballot_sync(0xffffffffu, mv != 0);
    unsigned word;
    if (anym == 0) {
        word = (wofs == 0) ? 2u : 0u;
    } else {
        int v = lut[(size_t)node * 4096 + (size_t)wofs * 32 + lane];
        word = __ballot_sync(0xffffffffu, v != 0);
    }
    if (lane == 0) g_lut[node * LUTW + wofs] = word;
}

__global__ void k_init(const int* __restrict__ init_states) {
    int i = blockIdx.x * blockDim.x + threadIdx.x;
    if (i == 0) { g_arrive = 0; g_gen = 0; }
    if (i >= ST_SZ) return;
    if (i < N_INPUT) {
        g_st[0][i] = g_u[i];                       // u[0][i]
    } else if (i < N_NODES) {
        int s = init_states[i];
        g_st[0][i] = s ? make_uint2(0xffffffffu, 0xffffffffu) : make_uint2(0u, 0u);
    } else {                                        // dummy + pad: zero both buffers
        g_st[0][i] = make_uint2(0u, 0u);
        g_st[1][i] = make_uint2(0u, 0u);
    }
}

// ---------------- main persistent kernel ----------------

__device__ __forceinline__ void grid_bar(int t, int nblocks) {
    __syncthreads();
    if (threadIdx.x == 0) {
        __threadfence();                                   // release this CTA's state writes
        unsigned tk = atomicAdd(&g_arrive, 1u);
        if (tk == (unsigned)(nblocks - 1)) {
            g_arrive = 0;
            __threadfence();
            g_gen = (unsigned)(t + 1);
        } else {
            while (g_gen <= (unsigned)t) { }               // volatile spin (L2)
        }
        __threadfence();
    }
    __syncthreads();
}

__global__ void __launch_bounds__(TPB_MAIN, 1) k_main() {
    const int lane = threadIdx.x & 31;
    const int gw   = blockIdx.x * (TPB_MAIN / 32) + (threadIdx.x >> 5);
    const int NW   = gridDim.x * (TPB_MAIN / 32);
    const int nb   = gridDim.x;
    int cur = 0;

    for (int t = 0; t < TSTEPS; t++) {
        const uint2* __restrict__ S = g_st[cur];
        uint2* __restrict__ D = g_st[cur ^ 1];

        // stage next step's input-layer bits into the destination buffer
        if (gw < 2 && t + 1 < TSTEPS) {
            int j = gw * 32 + lane;
            D[j] = g_u[(t + 1) * 64 + j];
        }

        for (int node = N_INPUT + gw; node < N_NODES; node += NW) {
            unsigned ai = (lane < KMAX) ? (unsigned)g_adj[node * 16 + lane] : (unsigned)DUMMY;
            uint2 w = __ldcg(&S[ai]);        // L2-coherent: L1 may hold stale lines from step t-2

            unsigned idxL = 0, idxH = 0;
#pragma unroll
            for (int k = 0; k < KMAX; k++) {
                unsigned lo = __shfl_sync(0xffffffffu, w.x, k);
                unsigned hi = __shfl_sync(0xffffffffu, w.y, k);
                idxL = (idxL << 1) | ((lo >> lane) & 1u);
                idxH = (idxH << 1) | ((hi >> lane) & 1u);
            }
            const unsigned* __restrict__ row = g_lut + node * LUTW;
            unsigned bl = (__ldg(&row[idxL >> 5]) >> (idxL & 31)) & 1u;
            unsigned bh = (__ldg(&row[idxH >> 5]) >> (idxH & 31)) & 1u;
            unsigned nlo = __ballot_sync(0xffffffffu, bl != 0);
            unsigned nhi = __ballot_sync(0xffffffffu, bh != 0);
            if (lane == 0) D[node] = make_uint2(nlo, nhi);
        }

        grid_bar(t, nb);
        cur ^= 1;
    }
}

// ---------------- readout: sigmoid(states[:,64:] @ W^T + b) ----------------

__global__ void k_readout(const float* __restrict__ W, const float* __restrict__ bias,
                          float* __restrict__ out) {
    int b   = blockIdx.x;        // 64 blocks
    int tid = threadIdx.x;       // 256 threads
    int lane = tid & 31, wrp = tid >> 5;
    const uint2* __restrict__ S = g_st[0];   // TSTEPS even -> final states in buffer 0

    float acc[N_OUT];
#pragma unroll
    for (int o = 0; o < N_OUT; o++) acc[o] = 0.f;

    const int bsh = b & 31;
    for (int n = N_INPUT + tid; n < N_NODES; n += blockDim.x) {
        uint2 w = S[n];
        unsigned word = (b < 32) ? w.x : w.y;
        float bit = (float)((word >> bsh) & 1u);
        const float* wp = W + (n - N_INPUT);
#pragma unroll
        for (int o = 0; o < N_OUT; o++)
            acc[o] += bit * wp[o * (N_NODES - N_INPUT)];
    }

    __shared__ float part[8][N_OUT];
#pragma unroll
    for (int o = 0; o < N_OUT; o++) {
        float v = acc[o];
#pragma unroll
        for (int off = 16; off; off >>= 1) v += __shfl_down_sync(0xffffffffu, v, off);
        if (lane == 0) part[wrp][o] = v;
    }
    __syncthreads();
    if (tid < N_OUT) {
        float s = bias[tid];
#pragma unroll
        for (int w2 = 0; w2 < 8; w2++) s += part[w2][tid];
        out[b * N_OUT + tid] = 1.0f / (1.0f + expf(-s));
    }
}

// ---------------- launch ----------------

extern "C" void kernel_launch(void* const* d_in, const int* in_sizes, int n_in,
                              void* d_out, int out_size) {
    (void)in_sizes; (void)n_in; (void)out_size;
    const int*   x           = (const int*)d_in[0];
    const int*   w_in        = (const int*)d_in[1];
    const int*   adj_list    = (const int*)d_in[2];
    const int*   adj_mask    = (const int*)d_in[3];
    const int*   lut         = (const int*)d_in[4];
    const int*   init_states = (const int*)d_in[5];
    const float* W_out       = (const float*)d_in[6];
    const float* b_out       = (const float*)d_in[7];
    float* out = (float*)d_out;

    k_pack_x<<<(NBATCH * TSTEPS * 32) / 256, 256>>>(x);
    k_pack_w<<<8, 256>>>(w_in);
    k_build_u<<<(TSTEPS * 64 * 32) / 256, 256>>>();
    k_pack_adj<<<(N_NODES + 255) / 256, 256>>>(adj_list, adj_mask);
    k_pack_lut<<<(N_NODES * LUTW) / 8, 256>>>(lut, adj_mask);
    k_init<<<(ST_SZ + 255) / 256, 256>>>(init_states);

    int dev = 0, sms = GRID_MAIN;
    cudaGetDevice(&dev);
    cudaDeviceGetAttribute(&sms, cudaDevAttrMultiProcessorCount, dev);
    int grid = (sms < GRID_MAIN) ? sms : GRID_MAIN;

    k_main<<<grid, TPB_MAIN>>>();
    k_readout<<<NBATCH, 256>>>(W_out, b_out, out);
}